// round 12
// baseline (speedup 1.0000x reference)
#include <cuda_runtime.h>
#include <cuda_fp16.h>
#include <math.h>
#include <stdlib.h>

#define NN 100000
#define EE 300000
#define XDIM 32
#define DDIM 256
#define NLAYER 3

// ---------------- scratch (<128MiB total: ~107MB) ----------------
__device__ float  g_big[NN * DDIM];    // xl_f16 | xr_f16 (as halfs)
__device__ int    g_esrc[EE];          // edge src, CSR-permuted
__device__ int    g_etp[EE];           // edge type, CSR-permuted
__device__ float  g_efp[EE];           // edge feat, CSR-permuted
__device__ int    g_rowptr[NN + 1];
__device__ int    g_cursor[NN];
__device__ double g_red[2];
__device__ float  g_stats[2];          // mu, rsigma of previous layer

namespace {
struct EnvSetter {
    EnvSetter() { setenv("CUDA_MODULE_LOADING", "EAGER", 1); }
};
EnvSetter g_env_setter;
}

// ---------------- CSR build ----------------
__global__ __launch_bounds__(256) void k_zero_cursor() {
    int i = blockIdx.x * blockDim.x + threadIdx.x;
    if (i < NN) g_cursor[i] = 0;
}

__global__ __launch_bounds__(256) void k_count(const int *__restrict__ ei) {
    int e = blockIdx.x * blockDim.x + threadIdx.x;
    if (e < EE) atomicAdd(&g_cursor[ei[EE + e]], 1);
}

__global__ __launch_bounds__(256, 1) void k_scan() {
    __shared__ int ssum[256];
    int t = threadIdx.x;
    const int CH = (NN + 255) / 256;
    int base = t * CH;
    int local = 0;
    for (int i = 0; i < CH; i++) {
        int idx = base + i;
        if (idx < NN) local += g_cursor[idx];
    }
    ssum[t] = local;
    __syncthreads();
    for (int off = 1; off < 256; off <<= 1) {
        int v = 0;
        if (t >= off) v = ssum[t - off];
        __syncthreads();
        if (t >= off) ssum[t] += v;
        __syncthreads();
    }
    int prefix = (t == 0) ? 0 : ssum[t - 1];
    for (int i = 0; i < CH; i++) {
        int idx = base + i;
        if (idx < NN) {
            int d = g_cursor[idx];
            g_rowptr[idx] = prefix;
            prefix += d;
        }
    }
    if (t == 255) g_rowptr[NN] = ssum[255];
}

__global__ __launch_bounds__(256) void k_copy_cursor() {
    int i = blockIdx.x * blockDim.x + threadIdx.x;
    if (i < NN) g_cursor[i] = g_rowptr[i];
}

// fill CSR-permuted edge arrays (src, type, feat) — per-layer reads become local
__global__ __launch_bounds__(256) void k_fill(const int *__restrict__ ei,
                                              const int *__restrict__ et,
                                              const float *__restrict__ ef) {
    int e = blockIdx.x * blockDim.x + threadIdx.x;
    if (e < EE) {
        int d = ei[EE + e];
        int pos = atomicAdd(&g_cursor[d], 1);
        g_esrc[pos] = ei[e];
        g_etp[pos] = et[e];
        g_efp[pos] = ef[e];
    }
}

// ---------------- pre-encoder ----------------
__global__ __launch_bounds__(256) void k_preenc(const float *__restrict__ x,
                                                const float *__restrict__ W0,
                                                const float *__restrict__ b0,
                                                float *__restrict__ h) {
    int n = blockIdx.x;
    int c = threadIdx.x;
    __shared__ float sx[XDIM];
    if (c < XDIM) sx[c] = x[n * XDIM + c];
    __syncthreads();
    float acc = b0[c];
#pragma unroll
    for (int k = 0; k < XDIM; k++) acc = fmaf(sx[k], W0[k * DDIM + c], acc);
    h[n * DDIM + c] = fmaxf(acc, 0.f);
}

// ---------------- tensor-core HGEMM, pipelined, optional fused LN on A ----------
#define BM 128
#define BN 128
#define BK 32

__device__ __forceinline__ unsigned smem_u32(const void *p) {
    return (unsigned)__cvta_generic_to_shared(p);
}

// load 16 fp32 A elems (optionally LN), convert to fp16 pairs
__device__ __forceinline__ void ldconvA(const float *__restrict__ A, long rowbase,
                                        int kcol, bool ok, int apply_ln, float mu,
                                        float rs, const float *__restrict__ gamma,
                                        const float *__restrict__ beta,
                                        uint4 &u0, uint4 &u1) {
    float v[16];
    if (ok) {
        const float4 *ap = (const float4 *)(A + rowbase + kcol);
        float4 f0 = ap[0], f1 = ap[1], f2 = ap[2], f3 = ap[3];
        v[0] = f0.x; v[1] = f0.y; v[2] = f0.z; v[3] = f0.w;
        v[4] = f1.x; v[5] = f1.y; v[6] = f1.z; v[7] = f1.w;
        v[8] = f2.x; v[9] = f2.y; v[10] = f2.z; v[11] = f2.w;
        v[12] = f3.x; v[13] = f3.y; v[14] = f3.z; v[15] = f3.w;
    } else {
#pragma unroll
        for (int i = 0; i < 16; i++) v[i] = 0.f;
    }
    if (apply_ln) {
        const float4 *gp = (const float4 *)(gamma + kcol);
        const float4 *bp = (const float4 *)(beta + kcol);
#pragma unroll
        for (int i = 0; i < 4; i++) {
            float4 g = gp[i], b = bp[i];
            float c0 = rs * g.x, c1 = rs * g.y, c2 = rs * g.z, c3 = rs * g.w;
            v[i * 4 + 0] = fmaf(v[i * 4 + 0], c0, b.x - mu * c0);
            v[i * 4 + 1] = fmaf(v[i * 4 + 1], c1, b.y - mu * c1);
            v[i * 4 + 2] = fmaf(v[i * 4 + 2], c2, b.z - mu * c2);
            v[i * 4 + 3] = fmaf(v[i * 4 + 3], c3, b.w - mu * c3);
        }
    }
    __half2 h0 = __floats2half2_rn(v[0], v[1]), h1 = __floats2half2_rn(v[2], v[3]);
    __half2 h2 = __floats2half2_rn(v[4], v[5]), h3 = __floats2half2_rn(v[6], v[7]);
    __half2 h4 = __floats2half2_rn(v[8], v[9]), h5 = __floats2half2_rn(v[10], v[11]);
    __half2 h6 = __floats2half2_rn(v[12], v[13]), h7 = __floats2half2_rn(v[14], v[15]);
    u0.x = *(unsigned *)&h0; u0.y = *(unsigned *)&h1;
    u0.z = *(unsigned *)&h2; u0.w = *(unsigned *)&h3;
    u1.x = *(unsigned *)&h4; u1.y = *(unsigned *)&h5;
    u1.z = *(unsigned *)&h6; u1.w = *(unsigned *)&h7;
}

__device__ __forceinline__ void ldconvB(const float *__restrict__ B, long base,
                                        uint4 &u0, uint4 &u1) {
    const float4 *bp = (const float4 *)(B + base);
    float4 f0 = bp[0], f1 = bp[1], f2 = bp[2], f3 = bp[3];
    __half2 h0 = __floats2half2_rn(f0.x, f0.y), h1 = __floats2half2_rn(f0.z, f0.w);
    __half2 h2 = __floats2half2_rn(f1.x, f1.y), h3 = __floats2half2_rn(f1.z, f1.w);
    __half2 h4 = __floats2half2_rn(f2.x, f2.y), h5 = __floats2half2_rn(f2.z, f2.w);
    __half2 h6 = __floats2half2_rn(f3.x, f3.y), h7 = __floats2half2_rn(f3.z, f3.w);
    u0.x = *(unsigned *)&h0; u0.y = *(unsigned *)&h1;
    u0.z = *(unsigned *)&h2; u0.w = *(unsigned *)&h3;
    u1.x = *(unsigned *)&h4; u1.y = *(unsigned *)&h5;
    u1.z = *(unsigned *)&h6; u1.w = *(unsigned *)&h7;
}

__global__ __launch_bounds__(256, 2) void k_hgemm(const float *__restrict__ A,
                                                  const float *__restrict__ Wl,
                                                  const float *__restrict__ Wr,
                                                  const float *__restrict__ blp,
                                                  const float *__restrict__ brp,
                                                  const float *__restrict__ gamma,
                                                  const float *__restrict__ beta,
                                                  int M, int apply_ln) {
    __shared__ __half sA[2][BM][BK + 8];
    __shared__ __half sB[2][BK][BN + 8];

    // linear grid: (mt, z, nt) with z/nt fastest -> 4 adjacent blocks share A tile (L2)
    int b = blockIdx.x;
    int mt = b >> 2, z = (b >> 1) & 1, nt = b & 1;
    const float *B = z ? Wr : Wl;
    const float *bias = z ? brp : blp;
    __half *C = reinterpret_cast<__half *>(g_big) + (long)z * NN * DDIM;

    int tid = threadIdx.x;
    int warp = tid >> 5, lane = tid & 31;
    int bm = mt * BM, bn = nt * BN;
    int wm = (warp & 3) * 32, wn = (warp >> 2) * 64;

    float mu = 0.f, rs = 1.f;
    if (apply_ln) { mu = g_stats[0]; rs = g_stats[1]; }

    float acc[2][8][4];
#pragma unroll
    for (int mi = 0; mi < 2; mi++)
#pragma unroll
        for (int ni = 0; ni < 8; ni++)
#pragma unroll
            for (int q = 0; q < 4; q++) acc[mi][ni][q] = 0.f;

    int ar = tid >> 1, ac = (tid & 1) * 16;
    int br_ = tid >> 3, bc = (tid & 7) * 16;
    bool avalid = (bm + ar) < M;
    long arowbase = (long)(bm + ar) * 256;

    uint4 ra0, ra1, rb0, rb1;
    // prologue: stage 0
    ldconvA(A, arowbase, 0 + ac, avalid, apply_ln, mu, rs, gamma, beta, ra0, ra1);
    ldconvB(B, (long)(0 + br_) * 256 + bn + bc, rb0, rb1);
    *(uint4 *)&sA[0][ar][ac] = ra0;
    *(uint4 *)&sA[0][ar][ac + 8] = ra1;
    *(uint4 *)&sB[0][br_][bc] = rb0;
    *(uint4 *)&sB[0][br_][bc + 8] = rb1;

    for (int k = 0; k < 8; k++) {
        __syncthreads();
        int cur = k & 1;
        if (k < 7) {
            int k0 = (k + 1) * BK;
            ldconvA(A, arowbase, k0 + ac, avalid, apply_ln, mu, rs, gamma, beta, ra0, ra1);
            ldconvB(B, (long)(k0 + br_) * 256 + bn + bc, rb0, rb1);
        }
#pragma unroll
        for (int kk = 0; kk < 2; kk++) {
            int ks = kk * 16;
            unsigned af[2][4];
#pragma unroll
            for (int mi = 0; mi < 2; mi++) {
                int row = wm + mi * 16 + (lane & 15);
                int col = ks + ((lane >> 4) << 3);
                unsigned addr = smem_u32(&sA[cur][row][col]);
                asm volatile(
                    "ldmatrix.sync.aligned.m8n8.x4.shared.b16 {%0,%1,%2,%3}, [%4];"
                    : "=r"(af[mi][0]), "=r"(af[mi][1]), "=r"(af[mi][2]), "=r"(af[mi][3])
                    : "r"(addr));
            }
            unsigned bf[8][2];
#pragma unroll
            for (int g = 0; g < 4; g++) {
                int row = ks + (lane & 15);
                int col = wn + g * 16 + ((lane >> 4) << 3);
                unsigned addr = smem_u32(&sB[cur][row][col]);
                unsigned r0, r1, r2, r3;
                asm volatile(
                    "ldmatrix.sync.aligned.m8n8.x4.trans.shared.b16 {%0,%1,%2,%3}, [%4];"
                    : "=r"(r0), "=r"(r1), "=r"(r2), "=r"(r3)
                    : "r"(addr));
                bf[g * 2][0] = r0; bf[g * 2][1] = r1;
                bf[g * 2 + 1][0] = r2; bf[g * 2 + 1][1] = r3;
            }
#pragma unroll
            for (int mi = 0; mi < 2; mi++)
#pragma unroll
                for (int ni = 0; ni < 8; ni++) {
                    asm volatile(
                        "mma.sync.aligned.m16n8k16.row.col.f32.f16.f16.f32 "
                        "{%0,%1,%2,%3}, {%4,%5,%6,%7}, {%8,%9}, {%0,%1,%2,%3};"
                        : "+f"(acc[mi][ni][0]), "+f"(acc[mi][ni][1]),
                          "+f"(acc[mi][ni][2]), "+f"(acc[mi][ni][3])
                        : "r"(af[mi][0]), "r"(af[mi][1]), "r"(af[mi][2]), "r"(af[mi][3]),
                          "r"(bf[ni][0]), "r"(bf[ni][1]));
                }
        }
        if (k < 7) {
            int nxt = 1 - cur;
            *(uint4 *)&sA[nxt][ar][ac] = ra0;
            *(uint4 *)&sA[nxt][ar][ac + 8] = ra1;
            *(uint4 *)&sB[nxt][br_][bc] = rb0;
            *(uint4 *)&sB[nxt][br_][bc + 8] = rb1;
        }
    }

    // epilogue: +bias, fp16, store
#pragma unroll
    for (int ni = 0; ni < 8; ni++) {
        int coln = bn + wn + ni * 8 + (lane & 3) * 2;
        float2 bv = *(const float2 *)&bias[coln];
#pragma unroll
        for (int mi = 0; mi < 2; mi++) {
            int row0 = bm + wm + mi * 16 + (lane >> 2);
            int row1 = row0 + 8;
            __half2 h01 = __floats2half2_rn(acc[mi][ni][0] + bv.x, acc[mi][ni][1] + bv.y);
            __half2 h23 = __floats2half2_rn(acc[mi][ni][2] + bv.x, acc[mi][ni][3] + bv.y);
            if (row0 < M) *(__half2 *)&C[(long)row0 * 256 + coln] = h01;
            if (row1 < M) *(__half2 *)&C[(long)row1 * 256 + coln] = h23;
        }
    }
}

// ---- fused: logits + single-pass online softmax aggregation + bo + relu + LN partials ----
__global__ __launch_bounds__(256) void k_agg_fused(const float *__restrict__ We,
                                                   const float *__restrict__ att,
                                                   const float *__restrict__ bo,
                                                   float *__restrict__ out) {
    __shared__ double sRed[8][2];
    int tid = threadIdx.x;
    int warp = tid >> 5, lane = tid & 31;
    int n = blockIdx.x * 8 + warp;
    double lsum = 0.0, lsq = 0.0;

    if (n < NN) {
        int c0 = lane * 8;
        const __half *xl = reinterpret_cast<const __half *>(g_big);
        const __half *xr = xl + (long)NN * DDIM;

        // per-lane channel constants in registers
        float w0[8], w1[8], w2[8], w3[8], attv[8], xrv[8];
        {
            float4 a0 = *(const float4 *)&We[c0], a1 = *(const float4 *)&We[c0 + 4];
            w0[0]=a0.x; w0[1]=a0.y; w0[2]=a0.z; w0[3]=a0.w; w0[4]=a1.x; w0[5]=a1.y; w0[6]=a1.z; w0[7]=a1.w;
            float4 b0_ = *(const float4 *)&We[DDIM + c0], b1 = *(const float4 *)&We[DDIM + c0 + 4];
            w1[0]=b0_.x; w1[1]=b0_.y; w1[2]=b0_.z; w1[3]=b0_.w; w1[4]=b1.x; w1[5]=b1.y; w1[6]=b1.z; w1[7]=b1.w;
            float4 c0_ = *(const float4 *)&We[2*DDIM + c0], c1 = *(const float4 *)&We[2*DDIM + c0 + 4];
            w2[0]=c0_.x; w2[1]=c0_.y; w2[2]=c0_.z; w2[3]=c0_.w; w2[4]=c1.x; w2[5]=c1.y; w2[6]=c1.z; w2[7]=c1.w;
            float4 d0 = *(const float4 *)&We[3*DDIM + c0], d1 = *(const float4 *)&We[3*DDIM + c0 + 4];
            w3[0]=d0.x; w3[1]=d0.y; w3[2]=d0.z; w3[3]=d0.w; w3[4]=d1.x; w3[5]=d1.y; w3[6]=d1.z; w3[7]=d1.w;
            float4 e0 = *(const float4 *)&att[c0], e1 = *(const float4 *)&att[c0 + 4];
            attv[0]=e0.x; attv[1]=e0.y; attv[2]=e0.z; attv[3]=e0.w; attv[4]=e1.x; attv[5]=e1.y; attv[6]=e1.z; attv[7]=e1.w;
            uint4 pr = *(const uint4 *)&xr[(long)n * DDIM + c0];
            const __half2 *hh = (const __half2 *)&pr;
#pragma unroll
            for (int q = 0; q < 4; q++) {
                float2 v = __half22float2(hh[q]);
                xrv[2 * q] = v.x; xrv[2 * q + 1] = v.y;
            }
        }

        int p0 = g_rowptr[n], p1 = g_rowptr[n + 1];
        float m = -INFINITY, s = 0.f;
        float acc[8] = {0.f, 0.f, 0.f, 0.f, 0.f, 0.f, 0.f, 0.f};

        for (int p = p0; p < p1; p++) {
            int src = g_esrc[p];
            int t = g_etp[p];
            float f = g_efp[p];
            uint4 pk = *(const uint4 *)&xl[(long)src * DDIM + c0];
            const __half2 *hh = (const __half2 *)&pk;
            float xv[8];
#pragma unroll
            for (int q = 0; q < 4; q++) {
                float2 v = __half22float2(hh[q]);
                xv[2 * q] = v.x; xv[2 * q + 1] = v.y;
            }
            float part = 0.f;
#pragma unroll
            for (int j = 0; j < 8; j++) {
                float wt = (t == 0) ? w0[j] : ((t == 1) ? w1[j] : w2[j]);
                float y = xv[j] + xrv[j] + wt + f * w3[j];
                y = (y > 0.f) ? y : 0.2f * y;
                part = fmaf(attv[j], y, part);
            }
            part += __shfl_xor_sync(0xffffffffu, part, 4);
            part += __shfl_xor_sync(0xffffffffu, part, 2);
            part += __shfl_xor_sync(0xffffffffu, part, 1);
            float mn = fmaxf(m, part);
            float sc = expf(m - mn);   // first edge: exp(-inf)=0
            float w = expf(part - mn);
            s = s * sc + w;
#pragma unroll
            for (int j = 0; j < 8; j++) acc[j] = fmaf(acc[j], sc, w * xv[j]);
            m = mn;
        }

        float inv_s = (p1 > p0) ? 1.f / s : 0.f;
        float bov[8];
        {
            float4 e0 = *(const float4 *)&bo[c0], e1 = *(const float4 *)&bo[c0 + 4];
            bov[0]=e0.x; bov[1]=e0.y; bov[2]=e0.z; bov[3]=e0.w; bov[4]=e1.x; bov[5]=e1.y; bov[6]=e1.z; bov[7]=e1.w;
        }
        float v[8];
#pragma unroll
        for (int j = 0; j < 8; j++) {
            float t2 = fmaf(acc[j], inv_s, bov[j]);
            t2 = fmaxf(t2, 0.f);
            v[j] = t2;
            lsum += (double)t2;
            lsq += (double)t2 * (double)t2;
        }
        *(float4 *)&out[(long)n * DDIM + c0] = make_float4(v[0], v[1], v[2], v[3]);
        *(float4 *)&out[(long)n * DDIM + c0 + 4] = make_float4(v[4], v[5], v[6], v[7]);
    }

#pragma unroll
    for (int off = 16; off; off >>= 1) {
        lsum += __shfl_xor_sync(0xffffffffu, lsum, off);
        lsq += __shfl_xor_sync(0xffffffffu, lsq, off);
    }
    if (lane == 0) {
        sRed[warp][0] = lsum;
        sRed[warp][1] = lsq;
    }
    __syncthreads();
    if (tid == 0) {
        double a = 0.0, b = 0.0;
        for (int w = 0; w < 8; w++) {
            a += sRed[w][0];
            b += sRed[w][1];
        }
        atomicAdd(&g_red[0], a);
        atomicAdd(&g_red[1], b);
    }
}

// ---------------- LN reset / finalize / apply (final layer only) ----------------
__global__ __launch_bounds__(32) void k_reset() {
    if (threadIdx.x == 0) {
        g_red[0] = 0.0;
        g_red[1] = 0.0;
    }
}

__global__ __launch_bounds__(32) void k_finalize() {
    const double cnt = (double)NN * (double)DDIM;
    double mu = g_red[0] / cnt;
    double var = g_red[1] / cnt - mu * mu;
    g_stats[0] = (float)mu;
    g_stats[1] = (float)rsqrt(var + 1e-5);
}

__global__ __launch_bounds__(256) void k_norm(float *__restrict__ h,
                                              const float *__restrict__ gamma,
                                              const float *__restrict__ beta) {
    long i = (long)blockIdx.x * blockDim.x + threadIdx.x;
    if (i >= (long)NN * (DDIM / 4)) return;
    float mu = g_stats[0], rs = g_stats[1];
    float4 v = ((float4 *)h)[i];
    int cb = ((int)(i & 63)) * 4;
    float4 ga = *(const float4 *)&gamma[cb];
    float4 be = *(const float4 *)&beta[cb];
    v.x = (v.x - mu) * rs * ga.x + be.x;
    v.y = (v.y - mu) * rs * ga.y + be.y;
    v.z = (v.z - mu) * rs * ga.z + be.z;
    v.w = (v.w - mu) * rs * ga.w + be.w;
    ((float4 *)h)[i] = v;
}

// ---------------- launch ----------------
extern "C" void kernel_launch(void *const *d_in, const int *in_sizes, int n_in,
                              void *d_out, int out_size) {
    const float *x = (const float *)d_in[0];
    const int *ei = (const int *)d_in[1];
    const int *et = (const int *)d_in[2];
    const float *ef = (const float *)d_in[3];
    const float *W0 = (const float *)d_in[4];
    const float *b0 = (const float *)d_in[5];
    const float *Wl = (const float *)d_in[6];
    const float *bl = (const float *)d_in[7];
    const float *Wr = (const float *)d_in[8];
    const float *br = (const float *)d_in[9];
    const float *We = (const float *)d_in[10];
    const float *att = (const float *)d_in[11];
    const float *bo = (const float *)d_in[12];
    const float *gamma = (const float *)d_in[13];
    const float *beta = (const float *)d_in[14];
    float *out = (float *)d_out;

    int nb = ((NN + BM - 1) / BM) * 4;  // (mt, z, nt) linearized

    // ordered so k_hgemm is the 4th launch (ncu capture slot)
    k_zero_cursor<<<(NN + 255) / 256, 256>>>();
    k_count<<<(EE + 255) / 256, 256>>>(ei);
    k_preenc<<<NN, DDIM>>>(x, W0, b0, out);
    k_hgemm<<<nb, 256>>>(out, Wl, Wr, bl, br, gamma, beta, NN, 0);  // layer 0
    k_scan<<<1, 256>>>();
    k_copy_cursor<<<(NN + 255) / 256, 256>>>();
    k_fill<<<(EE + 255) / 256, 256>>>(ei, et, ef);

    for (int l = 0; l < NLAYER; l++) {
        if (l > 0) {
            // hgemm reads pre-norm h' from out, applies previous layer's LN inline
            k_hgemm<<<nb, 256>>>(out, Wl + (long)l * DDIM * DDIM,
                                 Wr + (long)l * DDIM * DDIM, bl + l * DDIM,
                                 br + l * DDIM, gamma, beta, NN, 1);
        }
        k_reset<<<1, 32>>>();
        k_agg_fused<<<(NN + 7) / 8, 256>>>(We + (long)l * 4 * DDIM,
                                           att + (long)l * DDIM, bo + l * DDIM, out);
        k_finalize<<<1, 1>>>();
    }
    // final layer's LN applied explicitly (out must be normalized)
    k_norm<<<(NN * (DDIM / 4) + 255) / 256, 256>>>(out, gamma, beta);
}

// round 13
// speedup vs baseline: 1.0826x; 1.0826x over previous
#include <cuda_runtime.h>
#include <cuda_fp16.h>
#include <math.h>
#include <stdlib.h>

#define NN 100000
#define EE 300000
#define XDIM 32
#define DDIM 256
#define NLAYER 3

// ---------------- scratch (~110MB < 128MiB) ----------------
__device__ float  g_big[NN * DDIM];    // xl_f16 | xr_f16 (as halfs)
__device__ float  g_alpha[EE * 4];     // logits, CSR-permuted order
__device__ int    g_esrc[EE];          // edge src, CSR-permuted
__device__ int    g_pos[EE];           // edge -> CSR position
__device__ int    g_rowptr[NN + 1];
__device__ int    g_cursor[NN];
__device__ double g_red[2];
__device__ float  g_stats[2];          // mu, rsigma of previous layer LN

namespace {
struct EnvSetter {
    EnvSetter() { setenv("CUDA_MODULE_LOADING", "EAGER", 1); }
};
EnvSetter g_env_setter;
}

// ---------------- CSR build ----------------
__global__ __launch_bounds__(256) void k_zero_cursor() {
    int i = blockIdx.x * blockDim.x + threadIdx.x;
    if (i < NN) g_cursor[i] = 0;
}

__global__ __launch_bounds__(256) void k_count(const int *__restrict__ ei) {
    int e = blockIdx.x * blockDim.x + threadIdx.x;
    if (e < EE) atomicAdd(&g_cursor[ei[EE + e]], 1);
}

__global__ __launch_bounds__(256, 1) void k_scan() {
    __shared__ int ssum[256];
    int t = threadIdx.x;
    const int CH = (NN + 255) / 256;
    int base = t * CH;
    int local = 0;
    for (int i = 0; i < CH; i++) {
        int idx = base + i;
        if (idx < NN) local += g_cursor[idx];
    }
    ssum[t] = local;
    __syncthreads();
    for (int off = 1; off < 256; off <<= 1) {
        int v = 0;
        if (t >= off) v = ssum[t - off];
        __syncthreads();
        if (t >= off) ssum[t] += v;
        __syncthreads();
    }
    int prefix = (t == 0) ? 0 : ssum[t - 1];
    for (int i = 0; i < CH; i++) {
        int idx = base + i;
        if (idx < NN) {
            int d = g_cursor[idx];
            g_rowptr[idx] = prefix;
            prefix += d;
        }
    }
    if (t == 255) g_rowptr[NN] = ssum[255];
}

__global__ __launch_bounds__(256) void k_copy_cursor() {
    int i = blockIdx.x * blockDim.x + threadIdx.x;
    if (i < NN) g_cursor[i] = g_rowptr[i];
}

// record CSR position per edge; store src permuted
__global__ __launch_bounds__(256) void k_fill(const int *__restrict__ ei) {
    int e = blockIdx.x * blockDim.x + threadIdx.x;
    if (e < EE) {
        int d = ei[EE + e];
        int pos = atomicAdd(&g_cursor[d], 1);
        g_esrc[pos] = ei[e];
        g_pos[e] = pos;
    }
}

// ---------------- pre-encoder ----------------
__global__ __launch_bounds__(256) void k_preenc(const float *__restrict__ x,
                                                const float *__restrict__ W0,
                                                const float *__restrict__ b0,
                                                float *__restrict__ h) {
    int n = blockIdx.x;
    int c = threadIdx.x;
    __shared__ float sx[XDIM];
    if (c < XDIM) sx[c] = x[n * XDIM + c];
    __syncthreads();
    float acc = b0[c];
#pragma unroll
    for (int k = 0; k < XDIM; k++) acc = fmaf(sx[k], W0[k * DDIM + c], acc);
    h[n * DDIM + c] = fmaxf(acc, 0.f);
}

// ---------------- tensor-core HGEMM, pipelined, optional fused LN on A ----------
#define BM 128
#define BN 128
#define BK 32

__device__ __forceinline__ unsigned smem_u32(const void *p) {
    return (unsigned)__cvta_generic_to_shared(p);
}

__device__ __forceinline__ void ldconvA(const float *__restrict__ A, long rowbase,
                                        int kcol, bool ok, int apply_ln, float mu,
                                        float rs, const float *__restrict__ gamma,
                                        const float *__restrict__ beta,
                                        uint4 &u0, uint4 &u1) {
    float v[16];
    if (ok) {
        const float4 *ap = (const float4 *)(A + rowbase + kcol);
        float4 f0 = ap[0], f1 = ap[1], f2 = ap[2], f3 = ap[3];
        v[0] = f0.x; v[1] = f0.y; v[2] = f0.z; v[3] = f0.w;
        v[4] = f1.x; v[5] = f1.y; v[6] = f1.z; v[7] = f1.w;
        v[8] = f2.x; v[9] = f2.y; v[10] = f2.z; v[11] = f2.w;
        v[12] = f3.x; v[13] = f3.y; v[14] = f3.z; v[15] = f3.w;
    } else {
#pragma unroll
        for (int i = 0; i < 16; i++) v[i] = 0.f;
    }
    if (apply_ln) {
        const float4 *gp = (const float4 *)(gamma + kcol);
        const float4 *bp = (const float4 *)(beta + kcol);
#pragma unroll
        for (int i = 0; i < 4; i++) {
            float4 g = gp[i], b = bp[i];
            float c0 = rs * g.x, c1 = rs * g.y, c2 = rs * g.z, c3 = rs * g.w;
            v[i * 4 + 0] = fmaf(v[i * 4 + 0], c0, b.x - mu * c0);
            v[i * 4 + 1] = fmaf(v[i * 4 + 1], c1, b.y - mu * c1);
            v[i * 4 + 2] = fmaf(v[i * 4 + 2], c2, b.z - mu * c2);
            v[i * 4 + 3] = fmaf(v[i * 4 + 3], c3, b.w - mu * c3);
        }
    }
    __half2 h0 = __floats2half2_rn(v[0], v[1]), h1 = __floats2half2_rn(v[2], v[3]);
    __half2 h2 = __floats2half2_rn(v[4], v[5]), h3 = __floats2half2_rn(v[6], v[7]);
    __half2 h4 = __floats2half2_rn(v[8], v[9]), h5 = __floats2half2_rn(v[10], v[11]);
    __half2 h6 = __floats2half2_rn(v[12], v[13]), h7 = __floats2half2_rn(v[14], v[15]);
    u0.x = *(unsigned *)&h0; u0.y = *(unsigned *)&h1;
    u0.z = *(unsigned *)&h2; u0.w = *(unsigned *)&h3;
    u1.x = *(unsigned *)&h4; u1.y = *(unsigned *)&h5;
    u1.z = *(unsigned *)&h6; u1.w = *(unsigned *)&h7;
}

__device__ __forceinline__ void ldconvB(const float *__restrict__ B, long base,
                                        uint4 &u0, uint4 &u1) {
    const float4 *bp = (const float4 *)(B + base);
    float4 f0 = bp[0], f1 = bp[1], f2 = bp[2], f3 = bp[3];
    __half2 h0 = __floats2half2_rn(f0.x, f0.y), h1 = __floats2half2_rn(f0.z, f0.w);
    __half2 h2 = __floats2half2_rn(f1.x, f1.y), h3 = __floats2half2_rn(f1.z, f1.w);
    __half2 h4 = __floats2half2_rn(f2.x, f2.y), h5 = __floats2half2_rn(f2.z, f2.w);
    __half2 h6 = __floats2half2_rn(f3.x, f3.y), h7 = __floats2half2_rn(f3.z, f3.w);
    u0.x = *(unsigned *)&h0; u0.y = *(unsigned *)&h1;
    u0.z = *(unsigned *)&h2; u0.w = *(unsigned *)&h3;
    u1.x = *(unsigned *)&h4; u1.y = *(unsigned *)&h5;
    u1.z = *(unsigned *)&h6; u1.w = *(unsigned *)&h7;
}

__global__ __launch_bounds__(256, 2) void k_hgemm(const float *__restrict__ A,
                                                  const float *__restrict__ Wl,
                                                  const float *__restrict__ Wr,
                                                  const float *__restrict__ blp,
                                                  const float *__restrict__ brp,
                                                  const float *__restrict__ gamma,
                                                  const float *__restrict__ beta,
                                                  int M, int apply_ln) {
    __shared__ __half sA[2][BM][BK + 8];
    __shared__ __half sB[2][BK][BN + 8];

    int b = blockIdx.x;
    int mt = b >> 2, z = (b >> 1) & 1, nt = b & 1;
    const float *B = z ? Wr : Wl;
    const float *bias = z ? brp : blp;
    __half *C = reinterpret_cast<__half *>(g_big) + (long)z * NN * DDIM;

    int tid = threadIdx.x;
    int warp = tid >> 5, lane = tid & 31;
    int bm = mt * BM, bn = nt * BN;
    int wm = (warp & 3) * 32, wn = (warp >> 2) * 64;

    float mu = 0.f, rs = 1.f;
    if (apply_ln) { mu = g_stats[0]; rs = g_stats[1]; }

    float acc[2][8][4];
#pragma unroll
    for (int mi = 0; mi < 2; mi++)
#pragma unroll
        for (int ni = 0; ni < 8; ni++)
#pragma unroll
            for (int q = 0; q < 4; q++) acc[mi][ni][q] = 0.f;

    int ar = tid >> 1, ac = (tid & 1) * 16;
    int br_ = tid >> 3, bc = (tid & 7) * 16;
    bool avalid = (bm + ar) < M;
    long arowbase = (long)(bm + ar) * 256;

    uint4 ra0, ra1, rb0, rb1;
    ldconvA(A, arowbase, ac, avalid, apply_ln, mu, rs, gamma, beta, ra0, ra1);
    ldconvB(B, (long)br_ * 256 + bn + bc, rb0, rb1);
    *(uint4 *)&sA[0][ar][ac] = ra0;
    *(uint4 *)&sA[0][ar][ac + 8] = ra1;
    *(uint4 *)&sB[0][br_][bc] = rb0;
    *(uint4 *)&sB[0][br_][bc + 8] = rb1;

    for (int k = 0; k < 8; k++) {
        __syncthreads();
        int cur = k & 1;
        if (k < 7) {
            int k0 = (k + 1) * BK;
            ldconvA(A, arowbase, k0 + ac, avalid, apply_ln, mu, rs, gamma, beta, ra0, ra1);
            ldconvB(B, (long)(k0 + br_) * 256 + bn + bc, rb0, rb1);
        }
#pragma unroll
        for (int kk = 0; kk < 2; kk++) {
            int ks = kk * 16;
            unsigned af[2][4];
#pragma unroll
            for (int mi = 0; mi < 2; mi++) {
                int row = wm + mi * 16 + (lane & 15);
                int col = ks + ((lane >> 4) << 3);
                unsigned addr = smem_u32(&sA[cur][row][col]);
                asm volatile(
                    "ldmatrix.sync.aligned.m8n8.x4.shared.b16 {%0,%1,%2,%3}, [%4];"
                    : "=r"(af[mi][0]), "=r"(af[mi][1]), "=r"(af[mi][2]), "=r"(af[mi][3])
                    : "r"(addr));
            }
            unsigned bf[8][2];
#pragma unroll
            for (int g = 0; g < 4; g++) {
                int row = ks + (lane & 15);
                int col = wn + g * 16 + ((lane >> 4) << 3);
                unsigned addr = smem_u32(&sB[cur][row][col]);
                unsigned r0, r1, r2, r3;
                asm volatile(
                    "ldmatrix.sync.aligned.m8n8.x4.trans.shared.b16 {%0,%1,%2,%3}, [%4];"
                    : "=r"(r0), "=r"(r1), "=r"(r2), "=r"(r3)
                    : "r"(addr));
                bf[g * 2][0] = r0; bf[g * 2][1] = r1;
                bf[g * 2 + 1][0] = r2; bf[g * 2 + 1][1] = r3;
            }
#pragma unroll
            for (int mi = 0; mi < 2; mi++)
#pragma unroll
                for (int ni = 0; ni < 8; ni++) {
                    asm volatile(
                        "mma.sync.aligned.m16n8k16.row.col.f32.f16.f16.f32 "
                        "{%0,%1,%2,%3}, {%4,%5,%6,%7}, {%8,%9}, {%0,%1,%2,%3};"
                        : "+f"(acc[mi][ni][0]), "+f"(acc[mi][ni][1]),
                          "+f"(acc[mi][ni][2]), "+f"(acc[mi][ni][3])
                        : "r"(af[mi][0]), "r"(af[mi][1]), "r"(af[mi][2]), "r"(af[mi][3]),
                          "r"(bf[ni][0]), "r"(bf[ni][1]));
                }
        }
        if (k < 7) {
            int nxt = 1 - cur;
            *(uint4 *)&sA[nxt][ar][ac] = ra0;
            *(uint4 *)&sA[nxt][ar][ac + 8] = ra1;
            *(uint4 *)&sB[nxt][br_][bc] = rb0;
            *(uint4 *)&sB[nxt][br_][bc + 8] = rb1;
        }
    }

#pragma unroll
    for (int ni = 0; ni < 8; ni++) {
        int coln = bn + wn + ni * 8 + (lane & 3) * 2;
        float2 bv = *(const float2 *)&bias[coln];
#pragma unroll
        for (int mi = 0; mi < 2; mi++) {
            int row0 = bm + wm + mi * 16 + (lane >> 2);
            int row1 = row0 + 8;
            __half2 h01 = __floats2half2_rn(acc[mi][ni][0] + bv.x, acc[mi][ni][1] + bv.y);
            __half2 h23 = __floats2half2_rn(acc[mi][ni][2] + bv.x, acc[mi][ni][3] + bv.y);
            if (row0 < M) *(__half2 *)&C[(long)row0 * 256 + coln] = h01;
            if (row1 < M) *(__half2 *)&C[(long)row1 * 256 + coln] = h23;
        }
    }
}

// ---------------- edge logits: warp per edge, write alpha in CSR position -------
__global__ __launch_bounds__(256) void k_logits(const int *__restrict__ ei,
                                                const int *__restrict__ etype,
                                                const float *__restrict__ efeat,
                                                const float *__restrict__ We,
                                                const float *__restrict__ att) {
    __shared__ float sWe[4 * DDIM];
    __shared__ float sAtt[DDIM];
    int tid = threadIdx.x;
    for (int i = tid; i < 4 * DDIM; i += 256) sWe[i] = We[i];
    sAtt[tid] = att[tid];
    __syncthreads();

    int e = blockIdx.x * 8 + (tid >> 5);
    if (e >= EE) return;
    int lane = tid & 31;
    int src = ei[e];
    int dst = ei[EE + e];
    int t = etype[e];
    float f = efeat[e];
    int pos = g_pos[e];

    const __half *xl = reinterpret_cast<const __half *>(g_big);
    const __half *xr = xl + (long)NN * DDIM;
    int c0 = lane * 8;
    uint4 pl = *(const uint4 *)&xl[(long)src * DDIM + c0];
    uint4 pr = *(const uint4 *)&xr[(long)dst * DDIM + c0];
    const __half2 *hl = (const __half2 *)&pl;
    const __half2 *hr = (const __half2 *)&pr;

    float part = 0.f;
#pragma unroll
    for (int q = 0; q < 4; q++) {
        float2 a2 = __half22float2(hl[q]);
        float2 b2 = __half22float2(hr[q]);
        int c = c0 + q * 2;
        float y0 = a2.x + b2.x + sWe[t * DDIM + c] + f * sWe[3 * DDIM + c];
        float y1 = a2.y + b2.y + sWe[t * DDIM + c + 1] + f * sWe[3 * DDIM + c + 1];
        y0 = (y0 > 0.f) ? y0 : 0.2f * y0;
        y1 = (y1 > 0.f) ? y1 : 0.2f * y1;
        part = fmaf(sAtt[c], y0, part);
        part = fmaf(sAtt[c + 1], y1, part);
    }
#pragma unroll
    for (int off = 4; off; off >>= 1) part += __shfl_xor_sync(0xffffffffu, part, off);
    if ((lane & 7) == 0) g_alpha[pos * 4 + (lane >> 3)] = part;
}

// ---- softmax + per-head aggregation of xl_f16 + bo + relu + LN partials -> out ----
__global__ __launch_bounds__(256) void k_agg_out(const float *__restrict__ bo,
                                                 float *__restrict__ out) {
    __shared__ float sBo[DDIM];
    __shared__ double sRed[8][2];
    int tid = threadIdx.x;
    sBo[tid] = bo[tid];
    __syncthreads();

    int warp = tid >> 5, lane = tid & 31;
    int n = blockIdx.x * 8 + warp;
    double lsum = 0.0, lsq = 0.0;

    if (n < NN) {
        int hd = lane >> 3;
        int c0 = lane * 8;
        int p0 = g_rowptr[n], p1 = g_rowptr[n + 1];

        // pass 1: online max+sum over sequential alpha
        float m = -INFINITY, s = 0.f;
        for (int p = p0; p < p1; p++) {
            float a = g_alpha[p * 4 + hd];
            float mn = fmaxf(m, a);
            s = s * expf(m - mn) + expf(a - mn);
            m = mn;
        }
        float inv_s = (p1 > p0) ? 1.f / s : 0.f;

        // pass 2: weighted gather of xl_f16 (src sequential in CSR order)
        const __half *xl = reinterpret_cast<const __half *>(g_big);
        float acc[8] = {0.f, 0.f, 0.f, 0.f, 0.f, 0.f, 0.f, 0.f};
        for (int p = p0; p < p1; p++) {
            int src = g_esrc[p];
            float a = g_alpha[p * 4 + hd];
            float w = expf(a - m) * inv_s;
            uint4 pk = *(const uint4 *)&xl[(long)src * DDIM + c0];
            const __half2 *hh = (const __half2 *)&pk;
#pragma unroll
            for (int q = 0; q < 4; q++) {
                float2 v = __half22float2(hh[q]);
                acc[2 * q] = fmaf(w, v.x, acc[2 * q]);
                acc[2 * q + 1] = fmaf(w, v.y, acc[2 * q + 1]);
            }
        }

        float v[8];
#pragma unroll
        for (int j = 0; j < 8; j++) {
            float t2 = acc[j] + sBo[c0 + j];
            t2 = fmaxf(t2, 0.f);
            v[j] = t2;
            lsum += (double)t2;
            lsq += (double)t2 * (double)t2;
        }
        *(float4 *)&out[(long)n * DDIM + c0] = make_float4(v[0], v[1], v[2], v[3]);
        *(float4 *)&out[(long)n * DDIM + c0 + 4] = make_float4(v[4], v[5], v[6], v[7]);
    }

#pragma unroll
    for (int off = 16; off; off >>= 1) {
        lsum += __shfl_xor_sync(0xffffffffu, lsum, off);
        lsq += __shfl_xor_sync(0xffffffffu, lsq, off);
    }
    if (lane == 0) {
        sRed[warp][0] = lsum;
        sRed[warp][1] = lsq;
    }
    __syncthreads();
    if (tid == 0) {
        double a = 0.0, b = 0.0;
        for (int w = 0; w < 8; w++) {
            a += sRed[w][0];
            b += sRed[w][1];
        }
        atomicAdd(&g_red[0], a);
        atomicAdd(&g_red[1], b);
    }
}

// ---------------- LN reset / finalize / apply (final layer only) ----------------
__global__ __launch_bounds__(32) void k_reset() {
    if (threadIdx.x == 0) {
        g_red[0] = 0.0;
        g_red[1] = 0.0;
    }
}

__global__ __launch_bounds__(32) void k_finalize() {
    const double cnt = (double)NN * (double)DDIM;
    double mu = g_red[0] / cnt;
    double var = g_red[1] / cnt - mu * mu;
    g_stats[0] = (float)mu;
    g_stats[1] = (float)rsqrt(var + 1e-5);
}

__global__ __launch_bounds__(256) void k_norm(float *__restrict__ h,
                                              const float *__restrict__ gamma,
                                              const float *__restrict__ beta) {
    long i = (long)blockIdx.x * blockDim.x + threadIdx.x;
    if (i >= (long)NN * (DDIM / 4)) return;
    float mu = g_stats[0], rs = g_stats[1];
    float4 v = ((float4 *)h)[i];
    int cb = ((int)(i & 63)) * 4;
    float4 ga = *(const float4 *)&gamma[cb];
    float4 be = *(const float4 *)&beta[cb];
    v.x = (v.x - mu) * rs * ga.x + be.x;
    v.y = (v.y - mu) * rs * ga.y + be.y;
    v.z = (v.z - mu) * rs * ga.z + be.z;
    v.w = (v.w - mu) * rs * ga.w + be.w;
    ((float4 *)h)[i] = v;
}

// ---------------- launch ----------------
extern "C" void kernel_launch(void *const *d_in, const int *in_sizes, int n_in,
                              void *d_out, int out_size) {
    const float *x = (const float *)d_in[0];
    const int *ei = (const int *)d_in[1];
    const int *et = (const int *)d_in[2];
    const float *ef = (const float *)d_in[3];
    const float *W0 = (const float *)d_in[4];
    const float *b0 = (const float *)d_in[5];
    const float *Wl = (const float *)d_in[6];
    const float *bl = (const float *)d_in[7];
    const float *Wr = (const float *)d_in[8];
    const float *br = (const float *)d_in[9];
    const float *We = (const float *)d_in[10];
    const float *att = (const float *)d_in[11];
    const float *bo = (const float *)d_in[12];
    const float *gamma = (const float *)d_in[13];
    const float *beta = (const float *)d_in[14];
    float *out = (float *)d_out;

    int nb = ((NN + BM - 1) / BM) * 4;

    // hgemm as 4th launch (ncu capture slot)
    k_zero_cursor<<<(NN + 255) / 256, 256>>>();
    k_count<<<(EE + 255) / 256, 256>>>(ei);
    k_preenc<<<NN, DDIM>>>(x, W0, b0, out);
    k_hgemm<<<nb, 256>>>(out, Wl, Wr, bl, br, gamma, beta, NN, 0);  // layer 0
    k_scan<<<1, 256>>>();
    k_copy_cursor<<<(NN + 255) / 256, 256>>>();
    k_fill<<<(EE + 255) / 256, 256>>>(ei);

    for (int l = 0; l < NLAYER; l++) {
        if (l > 0) {
            k_hgemm<<<nb, 256>>>(out, Wl + (long)l * DDIM * DDIM,
                                 Wr + (long)l * DDIM * DDIM, bl + l * DDIM,
                                 br + l * DDIM, gamma, beta, NN, 1);
        }
        k_logits<<<(EE + 7) / 8, 256>>>(ei, et, ef, We + (long)l * 4 * DDIM,
                                        att + (long)l * DDIM);
        k_reset<<<1, 32>>>();
        k_agg_out<<<(NN + 7) / 8, 256>>>(bo + l * DDIM, out);
        k_finalize<<<1, 1>>>();
    }
    k_norm<<<(NN * (DDIM / 4) + 255) / 256, 256>>>(out, gamma, beta);
}

// round 14
// speedup vs baseline: 1.3036x; 1.2042x over previous
#include <cuda_runtime.h>
#include <cuda_fp16.h>
#include <math.h>
#include <stdlib.h>

#define NN 100000
#define EE 300000
#define XDIM 32
#define DDIM 256
#define NLAYER 3

// ---------------- scratch (~113MB < 128MiB) ----------------
__device__ float  g_big[NN * DDIM];    // xl_f16 | xr_f16 (as halfs)
__device__ float  g_alpha[EE * 4];     // logits, CSR order
__device__ int    g_esrc[EE];          // CSR-permuted edge data
__device__ int    g_edst[EE];
__device__ int    g_etp[EE];
__device__ float  g_efp[EE];
__device__ int    g_rowptr[NN + 1];
__device__ int    g_cursor[NN];
__device__ __half g_wp[2 * DDIM * DDIM];  // per-layer fp16 (LN-folded) Wl|Wr
__device__ float  g_bp[2 * DDIM];         // per-layer folded bias
__device__ double g_red[2];
__device__ float  g_stats[2];             // mu, rsigma of previous layer LN

namespace {
struct EnvSetter {
    EnvSetter() { setenv("CUDA_MODULE_LOADING", "EAGER", 1); }
};
EnvSetter g_env_setter;
}

// ---------------- CSR build ----------------
__global__ __launch_bounds__(256) void k_zero_cursor() {
    int i = blockIdx.x * blockDim.x + threadIdx.x;
    if (i < NN) g_cursor[i] = 0;
}

__global__ __launch_bounds__(256) void k_count(const int *__restrict__ ei) {
    int e = blockIdx.x * blockDim.x + threadIdx.x;
    if (e < EE) atomicAdd(&g_cursor[ei[EE + e]], 1);
}

__global__ __launch_bounds__(256, 1) void k_scan() {
    __shared__ int ssum[256];
    int t = threadIdx.x;
    const int CH = (NN + 255) / 256;
    int base = t * CH;
    int local = 0;
    for (int i = 0; i < CH; i++) {
        int idx = base + i;
        if (idx < NN) local += g_cursor[idx];
    }
    ssum[t] = local;
    __syncthreads();
    for (int off = 1; off < 256; off <<= 1) {
        int v = 0;
        if (t >= off) v = ssum[t - off];
        __syncthreads();
        if (t >= off) ssum[t] += v;
        __syncthreads();
    }
    int prefix = (t == 0) ? 0 : ssum[t - 1];
    for (int i = 0; i < CH; i++) {
        int idx = base + i;
        if (idx < NN) {
            int d = g_cursor[idx];
            g_rowptr[idx] = prefix;
            prefix += d;
        }
    }
    if (t == 255) g_rowptr[NN] = ssum[255];
}

__global__ __launch_bounds__(256) void k_copy_cursor() {
    int i = blockIdx.x * blockDim.x + threadIdx.x;
    if (i < NN) g_cursor[i] = g_rowptr[i];
}

__global__ __launch_bounds__(256) void k_fill(const int *__restrict__ ei,
                                              const int *__restrict__ et,
                                              const float *__restrict__ ef) {
    int e = blockIdx.x * blockDim.x + threadIdx.x;
    if (e < EE) {
        int d = ei[EE + e];
        int pos = atomicAdd(&g_cursor[d], 1);
        g_esrc[pos] = ei[e];
        g_edst[pos] = d;
        g_etp[pos] = et[e];
        g_efp[pos] = ef[e];
    }
}

// ---------------- pre-encoder: h_f16 = relu(x @ W0 + b0) -> d_out (as half) ------
__global__ __launch_bounds__(256) void k_preenc(const float *__restrict__ x,
                                                const float *__restrict__ W0,
                                                const float *__restrict__ b0,
                                                __half *__restrict__ h16) {
    int n = blockIdx.x;
    int c = threadIdx.x;
    __shared__ float sx[XDIM];
    if (c < XDIM) sx[c] = x[n * XDIM + c];
    __syncthreads();
    float acc = b0[c];
#pragma unroll
    for (int k = 0; k < XDIM; k++) acc = fmaf(sx[k], W0[k * DDIM + c], acc);
    h16[(long)n * DDIM + c] = __float2half_rn(fmaxf(acc, 0.f));
}

// ---------------- per-layer weight prep: fold LN into W', bias' ------------------
// W'[z][k][n] = f16( s[k] * W_z[k][n] ),  s[k] = apply_ln ? rs*gamma[k] : 1
__global__ __launch_bounds__(256) void k_wconv(const float *__restrict__ Wl,
                                               const float *__restrict__ Wr,
                                               const float *__restrict__ gamma,
                                               int apply_ln) {
    int b = blockIdx.x;          // 512 blocks: z*256 + k
    int z = b >> 8, k = b & 255;
    int n = threadIdx.x;
    const float *W = z ? Wr : Wl;
    float s = 1.f;
    if (apply_ln) s = g_stats[1] * gamma[k];
    g_wp[z * DDIM * DDIM + k * DDIM + n] = __float2half_rn(s * W[k * DDIM + n]);
}

// bias'[z][n] = bias_z[n] + sum_k c[k]*W_z[k][n],  c[k] = beta[k] - mu*rs*gamma[k]
__global__ __launch_bounds__(256) void k_bprep(const float *__restrict__ Wl,
                                               const float *__restrict__ Wr,
                                               const float *__restrict__ blp,
                                               const float *__restrict__ brp,
                                               const float *__restrict__ gamma,
                                               const float *__restrict__ beta,
                                               int apply_ln) {
    int z = blockIdx.x;
    int n = threadIdx.x;
    const float *W = z ? Wr : Wl;
    const float *bias = z ? brp : blp;
    float acc = bias[n];
    if (apply_ln) {
        float mu = g_stats[0], rs = g_stats[1];
        for (int k = 0; k < DDIM; k++) {
            float c = beta[k] - mu * rs * gamma[k];
            acc = fmaf(c, W[k * DDIM + n], acc);
        }
    }
    g_bp[z * DDIM + n] = acc;
}

// ---------------- pure-fp16 tensor-core GEMM ------------------------------------
#define BM 128
#define BN 128
#define BK 32

__device__ __forceinline__ unsigned smem_u32(const void *p) {
    return (unsigned)__cvta_generic_to_shared(p);
}

__global__ __launch_bounds__(256, 2) void k_hgemm(const __half *__restrict__ A16,
                                                  int M) {
    __shared__ __half sA[2][BM][BK + 8];
    __shared__ __half sB[2][BK][BN + 8];

    int b = blockIdx.x;
    int mt = b >> 2, z = (b >> 1) & 1, nt = b & 1;
    const __half *B = g_wp + z * DDIM * DDIM;
    const float *bias = g_bp + z * DDIM;
    __half *C = reinterpret_cast<__half *>(g_big) + (long)z * NN * DDIM;

    int tid = threadIdx.x;
    int warp = tid >> 5, lane = tid & 31;
    int bm = mt * BM, bn = nt * BN;
    int wm = (warp & 3) * 32, wn = (warp >> 2) * 64;

    float acc[2][8][4];
#pragma unroll
    for (int mi = 0; mi < 2; mi++)
#pragma unroll
        for (int ni = 0; ni < 8; ni++)
#pragma unroll
            for (int q = 0; q < 4; q++) acc[mi][ni][q] = 0.f;

    int ar = tid >> 1, ac = (tid & 1) * 16;   // A: 128 rows, 2 thr/row, 16 halfs each
    int br_ = tid >> 3, bc = (tid & 7) * 16;  // B: 32 rows, 8 thr/row, 16 halfs each
    bool avalid = (bm + ar) < M;
    long arowbase = (long)(bm + ar) * DDIM;

    uint4 ra0, ra1, rb0, rb1;
    // prologue (stage 0)
    {
        ra0 = make_uint4(0, 0, 0, 0); ra1 = ra0;
        if (avalid) {
            const uint4 *ap = (const uint4 *)(A16 + arowbase + ac);
            ra0 = ap[0]; ra1 = ap[1];
        }
        const uint4 *bp = (const uint4 *)(B + (long)br_ * DDIM + bn + bc);
        rb0 = bp[0]; rb1 = bp[1];
    }
    *(uint4 *)&sA[0][ar][ac] = ra0;
    *(uint4 *)&sA[0][ar][ac + 8] = ra1;
    *(uint4 *)&sB[0][br_][bc] = rb0;
    *(uint4 *)&sB[0][br_][bc + 8] = rb1;

    for (int k = 0; k < 8; k++) {
        __syncthreads();
        int cur = k & 1;
        if (k < 7) {
            int k0 = (k + 1) * BK;
            ra0 = make_uint4(0, 0, 0, 0); ra1 = ra0;
            if (avalid) {
                const uint4 *ap = (const uint4 *)(A16 + arowbase + k0 + ac);
                ra0 = ap[0]; ra1 = ap[1];
            }
            const uint4 *bp = (const uint4 *)(B + (long)(k0 + br_) * DDIM + bn + bc);
            rb0 = bp[0]; rb1 = bp[1];
        }
#pragma unroll
        for (int kk = 0; kk < 2; kk++) {
            int ks = kk * 16;
            unsigned af[2][4];
#pragma unroll
            for (int mi = 0; mi < 2; mi++) {
                int row = wm + mi * 16 + (lane & 15);
                int col = ks + ((lane >> 4) << 3);
                unsigned addr = smem_u32(&sA[cur][row][col]);
                asm volatile(
                    "ldmatrix.sync.aligned.m8n8.x4.shared.b16 {%0,%1,%2,%3}, [%4];"
                    : "=r"(af[mi][0]), "=r"(af[mi][1]), "=r"(af[mi][2]), "=r"(af[mi][3])
                    : "r"(addr));
            }
            unsigned bf[8][2];
#pragma unroll
            for (int g = 0; g < 4; g++) {
                int row = ks + (lane & 15);
                int col = wn + g * 16 + ((lane >> 4) << 3);
                unsigned addr = smem_u32(&sB[cur][row][col]);
                unsigned r0, r1, r2, r3;
                asm volatile(
                    "ldmatrix.sync.aligned.m8n8.x4.trans.shared.b16 {%0,%1,%2,%3}, [%4];"
                    : "=r"(r0), "=r"(r1), "=r"(r2), "=r"(r3)
                    : "r"(addr));
                bf[g * 2][0] = r0; bf[g * 2][1] = r1;
                bf[g * 2 + 1][0] = r2; bf[g * 2 + 1][1] = r3;
            }
#pragma unroll
            for (int mi = 0; mi < 2; mi++)
#pragma unroll
                for (int ni = 0; ni < 8; ni++) {
                    asm volatile(
                        "mma.sync.aligned.m16n8k16.row.col.f32.f16.f16.f32 "
                        "{%0,%1,%2,%3}, {%4,%5,%6,%7}, {%8,%9}, {%0,%1,%2,%3};"
                        : "+f"(acc[mi][ni][0]), "+f"(acc[mi][ni][1]),
                          "+f"(acc[mi][ni][2]), "+f"(acc[mi][ni][3])
                        : "r"(af[mi][0]), "r"(af[mi][1]), "r"(af[mi][2]), "r"(af[mi][3]),
                          "r"(bf[ni][0]), "r"(bf[ni][1]));
                }
        }
        if (k < 7) {
            int nxt = 1 - cur;
            *(uint4 *)&sA[nxt][ar][ac] = ra0;
            *(uint4 *)&sA[nxt][ar][ac + 8] = ra1;
            *(uint4 *)&sB[nxt][br_][bc] = rb0;
            *(uint4 *)&sB[nxt][br_][bc + 8] = rb1;
        }
    }

#pragma unroll
    for (int ni = 0; ni < 8; ni++) {
        int coln = bn + wn + ni * 8 + (lane & 3) * 2;
        float2 bv = *(const float2 *)&bias[coln];
#pragma unroll
        for (int mi = 0; mi < 2; mi++) {
            int row0 = bm + wm + mi * 16 + (lane >> 2);
            int row1 = row0 + 8;
            __half2 h01 = __floats2half2_rn(acc[mi][ni][0] + bv.x, acc[mi][ni][1] + bv.y);
            __half2 h23 = __floats2half2_rn(acc[mi][ni][2] + bv.x, acc[mi][ni][3] + bv.y);
            if (row0 < M) *(__half2 *)&C[(long)row0 * DDIM + coln] = h01;
            if (row1 < M) *(__half2 *)&C[(long)row1 * DDIM + coln] = h23;
        }
    }
}

// ---------------- edge logits: warp per CSR position (dst-sorted locality) -------
__global__ __launch_bounds__(256) void k_logits(const float *__restrict__ We,
                                                const float *__restrict__ att) {
    __shared__ float sWe[4 * DDIM];
    __shared__ float sAtt[DDIM];
    int tid = threadIdx.x;
    for (int i = tid; i < 4 * DDIM; i += 256) sWe[i] = We[i];
    sAtt[tid] = att[tid];
    __syncthreads();

    int p = blockIdx.x * 8 + (tid >> 5);
    if (p >= EE) return;
    int lane = tid & 31;
    int src = g_esrc[p];
    int dst = g_edst[p];
    int t = g_etp[p];
    float f = g_efp[p];

    const __half *xl = reinterpret_cast<const __half *>(g_big);
    const __half *xr = xl + (long)NN * DDIM;
    int c0 = lane * 8;
    uint4 pl = *(const uint4 *)&xl[(long)src * DDIM + c0];
    uint4 pr = *(const uint4 *)&xr[(long)dst * DDIM + c0];
    const __half2 *hl = (const __half2 *)&pl;
    const __half2 *hr = (const __half2 *)&pr;

    float part = 0.f;
#pragma unroll
    for (int q = 0; q < 4; q++) {
        float2 a2 = __half22float2(hl[q]);
        float2 b2 = __half22float2(hr[q]);
        int c = c0 + q * 2;
        float y0 = a2.x + b2.x + sWe[t * DDIM + c] + f * sWe[3 * DDIM + c];
        float y1 = a2.y + b2.y + sWe[t * DDIM + c + 1] + f * sWe[3 * DDIM + c + 1];
        y0 = (y0 > 0.f) ? y0 : 0.2f * y0;
        y1 = (y1 > 0.f) ? y1 : 0.2f * y1;
        part = fmaf(sAtt[c], y0, part);
        part = fmaf(sAtt[c + 1], y1, part);
    }
#pragma unroll
    for (int off = 4; off; off >>= 1) part += __shfl_xor_sync(0xffffffffu, part, off);
    if ((lane & 7) == 0) g_alpha[p * 4 + (lane >> 3)] = part;
}

// ---- softmax + per-head agg of xl_f16 + bo + relu + LN partials -----------------
// last==0: write fp16 h into out (as half, first half of d_out); last==1: fp32.
__global__ __launch_bounds__(256) void k_agg_out(const float *__restrict__ bo,
                                                 float *__restrict__ out, int last) {
    __shared__ float sBo[DDIM];
    __shared__ double sRed[8][2];
    int tid = threadIdx.x;
    sBo[tid] = bo[tid];
    __syncthreads();

    int warp = tid >> 5, lane = tid & 31;
    int n = blockIdx.x * 8 + warp;
    double lsum = 0.0, lsq = 0.0;

    if (n < NN) {
        int hd = lane >> 3;
        int c0 = lane * 8;
        int p0 = g_rowptr[n], p1 = g_rowptr[n + 1];

        float m = -INFINITY, s = 0.f;
        for (int p = p0; p < p1; p++) {
            float a = g_alpha[p * 4 + hd];
            float mn = fmaxf(m, a);
            s = s * expf(m - mn) + expf(a - mn);
            m = mn;
        }
        float inv_s = (p1 > p0) ? 1.f / s : 0.f;

        const __half *xl = reinterpret_cast<const __half *>(g_big);
        float acc[8] = {0.f, 0.f, 0.f, 0.f, 0.f, 0.f, 0.f, 0.f};
        for (int p = p0; p < p1; p++) {
            int src = g_esrc[p];
            float a = g_alpha[p * 4 + hd];
            float w = expf(a - m) * inv_s;
            uint4 pk = *(const uint4 *)&xl[(long)src * DDIM + c0];
            const __half2 *hh = (const __half2 *)&pk;
#pragma unroll
            for (int q = 0; q < 4; q++) {
                float2 v = __half22float2(hh[q]);
                acc[2 * q] = fmaf(w, v.x, acc[2 * q]);
                acc[2 * q + 1] = fmaf(w, v.y, acc[2 * q + 1]);
            }
        }

        float v[8];
#pragma unroll
        for (int j = 0; j < 8; j++) {
            float t2 = acc[j] + sBo[c0 + j];
            t2 = fmaxf(t2, 0.f);
            v[j] = t2;
            lsum += (double)t2;
            lsq += (double)t2 * (double)t2;
        }
        if (last) {
            *(float4 *)&out[(long)n * DDIM + c0] = make_float4(v[0], v[1], v[2], v[3]);
            *(float4 *)&out[(long)n * DDIM + c0 + 4] = make_float4(v[4], v[5], v[6], v[7]);
        } else {
            __half *h16 = reinterpret_cast<__half *>(out);
            __half2 a0 = __floats2half2_rn(v[0], v[1]);
            __half2 a1 = __floats2half2_rn(v[2], v[3]);
            __half2 a2 = __floats2half2_rn(v[4], v[5]);
            __half2 a3 = __floats2half2_rn(v[6], v[7]);
            uint4 pk;
            pk.x = *(unsigned *)&a0; pk.y = *(unsigned *)&a1;
            pk.z = *(unsigned *)&a2; pk.w = *(unsigned *)&a3;
            *(uint4 *)&h16[(long)n * DDIM + c0] = pk;
        }
    }

#pragma unroll
    for (int off = 16; off; off >>= 1) {
        lsum += __shfl_xor_sync(0xffffffffu, lsum, off);
        lsq += __shfl_xor_sync(0xffffffffu, lsq, off);
    }
    if (lane == 0) {
        sRed[warp][0] = lsum;
        sRed[warp][1] = lsq;
    }
    __syncthreads();
    if (tid == 0) {
        double a = 0.0, b = 0.0;
        for (int w = 0; w < 8; w++) {
            a += sRed[w][0];
            b += sRed[w][1];
        }
        atomicAdd(&g_red[0], a);
        atomicAdd(&g_red[1], b);
    }
}

// ---------------- LN reset / finalize / apply (final layer only) ----------------
__global__ __launch_bounds__(32) void k_reset() {
    if (threadIdx.x == 0) {
        g_red[0] = 0.0;
        g_red[1] = 0.0;
    }
}

__global__ __launch_bounds__(32) void k_finalize() {
    const double cnt = (double)NN * (double)DDIM;
    double mu = g_red[0] / cnt;
    double var = g_red[1] / cnt - mu * mu;
    g_stats[0] = (float)mu;
    g_stats[1] = (float)rsqrt(var + 1e-5);
}

__global__ __launch_bounds__(256) void k_norm(float *__restrict__ h,
                                              const float *__restrict__ gamma,
                                              const float *__restrict__ beta) {
    long i = (long)blockIdx.x * blockDim.x + threadIdx.x;
    if (i >= (long)NN * (DDIM / 4)) return;
    float mu = g_stats[0], rs = g_stats[1];
    float4 v = ((float4 *)h)[i];
    int cb = ((int)(i & 63)) * 4;
    float4 ga = *(const float4 *)&gamma[cb];
    float4 be = *(const float4 *)&beta[cb];
    v.x = (v.x - mu) * rs * ga.x + be.x;
    v.y = (v.y - mu) * rs * ga.y + be.y;
    v.z = (v.z - mu) * rs * ga.z + be.z;
    v.w = (v.w - mu) * rs * ga.w + be.w;
    ((float4 *)h)[i] = v;
}

// ---------------- launch ----------------
extern "C" void kernel_launch(void *const *d_in, const int *in_sizes, int n_in,
                              void *d_out, int out_size) {
    const float *x = (const float *)d_in[0];
    const int *ei = (const int *)d_in[1];
    const int *et = (const int *)d_in[2];
    const float *ef = (const float *)d_in[3];
    const float *W0 = (const float *)d_in[4];
    const float *b0 = (const float *)d_in[5];
    const float *Wl = (const float *)d_in[6];
    const float *bl = (const float *)d_in[7];
    const float *Wr = (const float *)d_in[8];
    const float *br = (const float *)d_in[9];
    const float *We = (const float *)d_in[10];
    const float *att = (const float *)d_in[11];
    const float *bo = (const float *)d_in[12];
    const float *gamma = (const float *)d_in[13];
    const float *beta = (const float *)d_in[14];
    float *out = (float *)d_out;
    __half *h16 = (__half *)d_out;

    int nb = ((NN + BM - 1) / BM) * 4;

    // layer 0 weight prep + pre-encoder, hgemm as 4th launch (ncu slot)
    k_wconv<<<512, 256>>>(Wl, Wr, gamma, 0);
    k_bprep<<<2, 256>>>(Wl, Wr, bl, br, gamma, beta, 0);
    k_preenc<<<NN, DDIM>>>(x, W0, b0, h16);
    k_hgemm<<<nb, 256>>>(h16, NN);

    // CSR build (independent of hgemm)
    k_zero_cursor<<<(NN + 255) / 256, 256>>>();
    k_count<<<(EE + 255) / 256, 256>>>(ei);
    k_scan<<<1, 256>>>();
    k_copy_cursor<<<(NN + 255) / 256, 256>>>();
    k_fill<<<(EE + 255) / 256, 256>>>(ei, et, ef);

    for (int l = 0; l < NLAYER; l++) {
        if (l > 0) {
            k_wconv<<<512, 256>>>(Wl + (long)l * DDIM * DDIM,
                                  Wr + (long)l * DDIM * DDIM, gamma, 1);
            k_bprep<<<2, 256>>>(Wl + (long)l * DDIM * DDIM,
                                Wr + (long)l * DDIM * DDIM, bl + l * DDIM,
                                br + l * DDIM, gamma, beta, 1);
            k_hgemm<<<nb, 256>>>(h16, NN);
        }
        k_logits<<<(EE + 7) / 8, 256>>>(We + (long)l * 4 * DDIM, att + (long)l * DDIM);
        k_reset<<<1, 32>>>();
        k_agg_out<<<(NN + 7) / 8, 256>>>(bo + l * DDIM, out, l == NLAYER - 1 ? 1 : 0);
        k_finalize<<<1, 1>>>();
    }
    k_norm<<<(NN * (DDIM / 4) + 255) / 256, 256>>>(out, gamma, beta);
}